// round 6
// baseline (speedup 1.0000x reference)
#include <cuda_runtime.h>
#include <cuda_fp16.h>
#include <cstdint>

#define BB 256
#define NN 2048
#define DD 128
#define RPB 2048
#define TILE_R 64
#define TILES (BB*32)             // 8192 tiles
#define GRID_MAIN 444             // 3 persistent CTAs/SM
// smem: W16 [0,32768) | buf (E16 16KB / D 33792B overlay) [32768,66560) | segs [66560,66816)
#define SMEM_MAIN 66816

// ---------------- device scratch ----------------
__device__ float g_acc[BB*DD];
__device__ int   g_hist[BB*BB];
__device__ int   g_perm[BB*RPB];
__device__ int   g_segs[BB*RPB];
__device__ float g_T[BB*DD];

// ---------------- helpers ----------------
static __device__ __forceinline__ uint32_t smem_u32(const void* p){
  uint32_t a;
  asm("{ .reg .u64 t; cvta.to.shared.u64 t, %1; cvt.u32.u64 %0, t; }" : "=r"(a) : "l"(p));
  return a;
}
static __device__ __forceinline__ uint32_t h2u(__half2 h){
  union { __half2 h; uint32_t u; } c; c.h = h; return c.u;
}
static __device__ __forceinline__ void ldsm4(uint32_t &r0, uint32_t &r1, uint32_t &r2, uint32_t &r3, uint32_t a){
  asm volatile("ldmatrix.sync.aligned.m8n8.x4.shared.b16 {%0,%1,%2,%3}, [%4];"
    : "=r"(r0), "=r"(r1), "=r"(r2), "=r"(r3) : "r"(a));
}
static __device__ __forceinline__ void mma16816(float* c, uint32_t a0, uint32_t a1, uint32_t a2, uint32_t a3,
                                                uint32_t b0, uint32_t b1){
  asm volatile("mma.sync.aligned.m16n8k16.row.col.f32.f16.f16.f32 "
    "{%0,%1,%2,%3}, {%4,%5,%6,%7}, {%8,%9}, {%0,%1,%2,%3};"
    : "+f"(c[0]), "+f"(c[1]), "+f"(c[2]), "+f"(c[3])
    : "r"(a0), "r"(a1), "r"(a2), "r"(a3), "r"(b0), "r"(b1));
}

// ---------------- fused prep (warp-shuffle scan, 4 syncs) ----------------
__global__ void __launch_bounds__(512) k_prep(const int* __restrict__ bidx,
                                              const float* __restrict__ embs,
                                              const float* __restrict__ W1,
                                              const float* __restrict__ b1){
  int b = blockIdx.x, t = threadIdx.x;
  if (b < BB){
    __shared__ int h[BB];
    __shared__ int wsum[8];
    if (t < BB) h[t] = 0;
    if (t < DD) g_acc[b*DD + t] = 0.f;
    __syncthreads();
    #pragma unroll
    for (int i = t; i < NN-1; i += 512)
      atomicAdd(&h[bidx[b*NN + 1 + i]], 1);
    __syncthreads();
    int lane = t & 31, wrp = t >> 5;
    int v = 0, x = 0;
    if (t < BB){ v = h[t]; g_hist[b*BB + t] = v; }
    x = v;
    #pragma unroll
    for (int o = 1; o < 32; o <<= 1){
      int y = __shfl_up_sync(0xffffffffu, x, o);
      if (lane >= o) x += y;
    }
    if (t < BB && lane == 31) wsum[wrp] = x;
    __syncthreads();
    if (t < 32){
      int s = (t < 8) ? wsum[t] : 0;
      #pragma unroll
      for (int o = 1; o < 8; o <<= 1){
        int y = __shfl_up_sync(0xffffffffu, s, o);
        if (t >= o) s += y;
      }
      if (t < 8) wsum[t] = s;
    }
    __syncthreads();
    if (t < BB){
      int off = (wrp > 0) ? wsum[wrp-1] : 0;
      h[t] = off + x - v;       // exclusive prefix = cursor
    }
    __syncthreads();
    #pragma unroll
    for (int i = t; i < NN-1; i += 512){
      int g = b*NN + 1 + i;
      int s = bidx[g];
      int pos = atomicAdd(&h[s], 1);
      g_perm[b*RPB + pos] = g;
      g_segs[b*RPB + pos] = s;
    }
    if (t == 0){ g_perm[b*RPB + NN-1] = b*NN + 1; g_segs[b*RPB + NN-1] = -1; }
  } else {
    int bb = b - BB;
    __shared__ float tg[DD];
    if (t < DD) tg[t] = embs[(size_t)bb*NN*DD + t];
    __syncthreads();
    if (t < DD){
      float s = b1[t];
      const float* w = W1 + (size_t)t*2*DD;
      #pragma unroll 8
      for (int k = 0; k < DD; k++) s += w[k]*tg[k];
      g_T[bb*DD + t] = s;
    }
  }
}

// ---------------- main persistent HMMA kernel: 3 CTAs/SM ----------------
__global__ void __launch_bounds__(128, 3) k_main(const float* __restrict__ embs,
                                                 const float* __restrict__ W1){
  extern __shared__ char sm[];
  float* Dm = (float*)(sm + 32768);
  int* segs = (int*)(sm + 66560);
  uint32_t sbase = smem_u32(sm);
  const uint32_t Wb = sbase, Eb = sbase + 32768;

  int tid = threadIdx.x;
  int lane = tid & 31, w = tid >> 5;

  // ---- convert W1b -> smem fp16 once (row d = tid) ----
  {
    const float4* wr = (const float4*)(W1 + (size_t)tid*2*DD + DD);
    uint32_t sw = (uint32_t)(tid & 7) << 4;
    char* dst = sm + tid*256;
    #pragma unroll
    for (int i = 0; i < 16; i++){
      float4 v0 = wr[2*i], v1 = wr[2*i+1];
      uint4 q;
      q.x = h2u(__floats2half2_rn(v0.x, v0.y));
      q.y = h2u(__floats2half2_rn(v0.z, v0.w));
      q.z = h2u(__floats2half2_rn(v1.x, v1.y));
      q.w = h2u(__floats2half2_rn(v1.z, v1.w));
      *(uint4*)(dst + (((uint32_t)(i*16)) ^ sw)) = q;
    }
  }

  // ldmatrix bases
  const uint32_t ln15 = lane & 15;
  const uint32_t sxor = (uint32_t)(lane & 7) << 4;
  const uint32_t kbl  = (uint32_t)(lane >> 4) << 4;
  const uint32_t baseA = Eb + (w*16 + ln15)*256;
  const uint32_t baseB = Wb + ln15*256;

  // gather mapping: thread -> row er, half eh (64 floats)
  const int er = tid >> 1, eh = tid & 1;
  char* edst = sm + 32768 + er*256;
  const uint32_t esw = (uint32_t)(er & 7) << 4;
  const uint32_t ecol = (uint32_t)eh << 7;   // byte offset of half within fp16 row

  for (int tile = blockIdx.x; tile < TILES; tile += GRID_MAIN){
    int btile = tile >> 5;
    int rowbase = btile*RPB + (tile & 31)*TILE_R;

    __syncthreads();   // previous tile's D + segs fully consumed

    // ---- gather 64 rows: LDG float4 -> fp16 -> swizzled STS ----
    {
      int g = g_perm[rowbase + er];
      const float4* src = (const float4*)(embs + (size_t)g*DD + eh*64);
      #pragma unroll
      for (int i = 0; i < 16; i++){
        float4 v = src[i];
        uint2 q;
        q.x = h2u(__floats2half2_rn(v.x, v.y));
        q.y = h2u(__floats2half2_rn(v.z, v.w));
        *(uint2*)(edst + ((ecol + (uint32_t)(i*8)) ^ esw)) = q;
      }
    }
    if (tid < TILE_R) segs[tid] = g_segs[rowbase + tid];
    __syncthreads();

    // ---- MMA: D[r][d], 64 rows x 128 cols, K=128 ----
    float acc[16][4];
    #pragma unroll
    for (int i = 0; i < 16; i++){
      acc[i][0] = 0.f; acc[i][1] = 0.f; acc[i][2] = 0.f; acc[i][3] = 0.f;
    }
    #pragma unroll
    for (int k0 = 0; k0 < 8; k0++){
      uint32_t ko = (((uint32_t)k0 << 5) | kbl) ^ sxor;
      uint32_t a0, a1, a2, a3;
      ldsm4(a0, a1, a2, a3, baseA + ko);
      uint32_t bad = baseB + ko;
      #pragma unroll
      for (int np = 0; np < 8; np++){
        uint32_t b0, b1, b2, b3;
        ldsm4(b0, b1, b2, b3, bad);
        bad += 16*256;
        mma16816(acc[2*np],   a0, a1, a2, a3, b0, b2);
        mma16816(acc[2*np+1], a0, a1, a2, a3, b1, b3);
      }
    }
    __syncthreads();   // all E reads done; D may overwrite

    // ---- store D (pad-132, conflict-free) ----
    {
      int r0 = w*16 + (lane >> 2);
      int c0 = 2*(lane & 3);
      #pragma unroll
      for (int nt = 0; nt < 16; nt++){
        *(float2*)(Dm + r0*132 + nt*8 + c0)     = make_float2(acc[nt][0], acc[nt][1]);
        *(float2*)(Dm + (r0+8)*132 + nt*8 + c0) = make_float2(acc[nt][2], acc[nt][3]);
      }
    }
    __syncthreads();

    // ---- epilogue: col d = tid; +T, relu, sorted run-length reduce ----
    {
      float t_d = g_T[btile*DD + tid];
      int cur = -1; float run = 0.f;
      #pragma unroll 8
      for (int r = 0; r < TILE_R; r++){
        int s = segs[r];
        float v = fmaxf(Dm[r*132 + tid] + t_d, 0.f);
        if (s != cur){
          if (cur >= 0) atomicAdd(&g_acc[cur*DD + tid], run);
          run = 0.f; cur = s;
        }
        if (s >= 0) run += v;
      }
      if (cur >= 0) atomicAdd(&g_acc[cur*DD + tid], run);
    }
  }
}

// ---------------- final: out[s] = W2 . acc[s] + b2 * count_s ----------------
__global__ void __launch_bounds__(128) k_final(const float* __restrict__ W2,
                                               const float* __restrict__ b2,
                                               float* __restrict__ out){
  __shared__ float arow[DD];
  __shared__ int red[DD];
  int s = blockIdx.x, d = threadIdx.x;
  arow[d] = g_acc[s*DD + d];
  red[d] = g_hist[d*BB + s] + g_hist[(d + 128)*BB + s];
  __syncthreads();
  #pragma unroll
  for (int o = 64; o > 0; o >>= 1){
    if (d < o) red[d] += red[d + o];
    __syncthreads();
  }
  float r = 0.f;
  const float* ww = W2 + (size_t)d*DD;
  #pragma unroll 8
  for (int j = 0; j < DD; j++) r += ww[j]*arow[j];
  out[s*DD + d] = r + b2[d]*(float)red[0];
}

// ---------------- launch ----------------
extern "C" void kernel_launch(void* const* d_in, const int* in_sizes, int n_in,
                              void* d_out, int out_size){
  const float* embs = (const float*)d_in[0];
  const float* W1   = (const float*)d_in[1];
  const float* b1   = (const float*)d_in[2];
  const float* W2   = (const float*)d_in[3];
  const float* b2   = (const float*)d_in[4];
  const int*   bidx = (const int*)d_in[5];
  float* out = (float*)d_out;

  cudaFuncSetAttribute(k_main, cudaFuncAttributeMaxDynamicSharedMemorySize, SMEM_MAIN);

  k_prep <<<2*BB, 512>>>(bidx, embs, W1, b1);
  k_main <<<GRID_MAIN, 128, SMEM_MAIN>>>(embs, W1);
  k_final<<<BB, DD>>>(W2, b2, out);
}